// round 15
// baseline (speedup 1.0000x reference)
#include <cuda_runtime.h>
#include <cuda_fp16.h>
#include <cstdint>

#define NROWS 8192
#define BHALF 4096
#define DIM   256
#define SS    72            // smem row stride (fp16): 64 data + 8 pad, conflict-free
#define STAGE (128 * SS)    // elems per array per pipeline stage (K=64 chunk)
#define STGB  (4 * STAGE)   // bytes per stage (A tile + B tile, fp16)
#define NTILE 64
#define NBLK  2080          // upper-triangular 64x64 tile count
#define SMEM_BYTES (3 * STGB)   // 3 stages = 110592 B
#define CB 256              // prep_cols blocks

// ---------------- scratch (device globals; no allocation) ----------------
__device__ __half g_Xh[NROWS * DIM];
__device__ float  g_sq[NROWS];
__device__ float  g_colpart[CB * DIM];
__device__ float  g_c1;            // -g0 * log2(e)
__device__ double g_Wpart[NBLK];
__device__ unsigned g_ctrM;        // main completion ticket

// ---------------- prep 1: per-row sq-norm + fp16 image (1024 blocks) ----------------
__global__ void prep_rows(const float* __restrict__ s, const float* __restrict__ t) {
    int warp = threadIdx.x >> 5, lane = threadIdx.x & 31;
    int row  = blockIdx.x * 8 + warp;
    const float* src = (row < BHALF) ? (s + (size_t)row * DIM)
                                     : (t + (size_t)(row - BHALF) * DIM);
    float4 v0 = *(const float4*)(src + lane * 8);
    float4 v1 = *(const float4*)(src + lane * 8 + 4);
    float v[8] = {v0.x, v0.y, v0.z, v0.w, v1.x, v1.y, v1.z, v1.w};

    float sq = 0.f;
    unsigned hu[4];
#pragma unroll
    for (int j = 0; j < 4; j++) {
        float a = v[2 * j], b = v[2 * j + 1];
        sq = fmaf(a, a, sq);
        sq = fmaf(b, b, sq);
        hu[j] = (unsigned)__half_as_ushort(__float2half_rn(a)) |
                ((unsigned)__half_as_ushort(__float2half_rn(b)) << 16);
    }
    *(uint4*)(g_Xh + (size_t)row * DIM + lane * 8) = make_uint4(hu[0], hu[1], hu[2], hu[3]);

#pragma unroll
    for (int o = 16; o; o >>= 1) sq += __shfl_xor_sync(0xffffffffu, sq, o);
    if (lane == 0) g_sq[row] = sq;
}

// ---------------- prep 2: column partial sums (256 blocks) ----------------
__global__ void prep_cols(const float* __restrict__ s, const float* __restrict__ t) {
    int d = threadIdx.x;           // 0..255
    int b = blockIdx.x;            // 0..CB-1
    float a0 = 0.f, a1 = 0.f, a2 = 0.f, a3 = 0.f;
#pragma unroll
    for (int r = 0; r < 32; r += 4) {
        int row = b * 32 + r;
        const float* p0 = (row + 0 < BHALF) ? (s + (size_t)(row + 0) * DIM) : (t + (size_t)(row + 0 - BHALF) * DIM);
        const float* p1 = (row + 1 < BHALF) ? (s + (size_t)(row + 1) * DIM) : (t + (size_t)(row + 1 - BHALF) * DIM);
        const float* p2 = (row + 2 < BHALF) ? (s + (size_t)(row + 2) * DIM) : (t + (size_t)(row + 2 - BHALF) * DIM);
        const float* p3 = (row + 3 < BHALF) ? (s + (size_t)(row + 3) * DIM) : (t + (size_t)(row + 3 - BHALF) * DIM);
        a0 += p0[d]; a1 += p1[d]; a2 += p2[d]; a3 += p3[d];
    }
    g_colpart[b * DIM + d] = (a0 + a1) + (a2 + a3);
}

// ---------------- prep 3: bandwidth scalar (1 block, MLP-8 chains) ----------------
__global__ void prep_scalar() {
    __shared__ double sh[256];
    int t = threadIdx.x;
    double S0 = 0, S1 = 0, S2 = 0, S3 = 0, S4 = 0, S5 = 0, S6 = 0, S7 = 0;
#pragma unroll
    for (int i = 0; i < 32; i += 8) {
        S0 += (double)g_sq[t + (i + 0) * 256];
        S1 += (double)g_sq[t + (i + 1) * 256];
        S2 += (double)g_sq[t + (i + 2) * 256];
        S3 += (double)g_sq[t + (i + 3) * 256];
        S4 += (double)g_sq[t + (i + 4) * 256];
        S5 += (double)g_sq[t + (i + 5) * 256];
        S6 += (double)g_sq[t + (i + 6) * 256];
        S7 += (double)g_sq[t + (i + 7) * 256];
    }
    double S = ((S0 + S1) + (S2 + S3)) + ((S4 + S5) + (S6 + S7));

    double c0 = 0, c1_ = 0, c2 = 0, c3 = 0, c4 = 0, c5 = 0, c6 = 0, c7 = 0;
#pragma unroll 4
    for (int b = 0; b < CB; b += 8) {
        c0 += (double)g_colpart[(b + 0) * DIM + t];
        c1_ += (double)g_colpart[(b + 1) * DIM + t];
        c2 += (double)g_colpart[(b + 2) * DIM + t];
        c3 += (double)g_colpart[(b + 3) * DIM + t];
        c4 += (double)g_colpart[(b + 4) * DIM + t];
        c5 += (double)g_colpart[(b + 5) * DIM + t];
        c6 += (double)g_colpart[(b + 6) * DIM + t];
        c7 += (double)g_colpart[(b + 7) * DIM + t];
    }
    double c = ((c0 + c1_) + (c2 + c3)) + ((c4 + c5) + (c6 + c7));

    sh[t] = 2.0 * (double)NROWS * S - 2.0 * c * c;
    __syncthreads();
    for (int o = 128; o; o >>= 1) {
        if (t < o) sh[t] += sh[t + o];
        __syncthreads();
    }
    if (t == 0) {
        double bw = ((double)NROWS * (double)NROWS - (double)NROWS) / sh[0];
        bw *= 0.25;  // / 2^(NUM_KERNELS//2)
        g_c1 = (float)(-bw * 1.4426950408889634);  // -g0 * log2(e)
    }
}

// ---------------- asm helpers ----------------
__device__ __forceinline__ void mma16816(float* c, const uint32_t* a, const uint32_t* b) {
    asm volatile(
        "mma.sync.aligned.m16n8k16.row.col.f32.f16.f16.f32 "
        "{%0,%1,%2,%3},{%4,%5,%6,%7},{%8,%9},{%0,%1,%2,%3};"
        : "+f"(c[0]), "+f"(c[1]), "+f"(c[2]), "+f"(c[3])
        : "r"(a[0]), "r"(a[1]), "r"(a[2]), "r"(a[3]), "r"(b[0]), "r"(b[1]));
}

__device__ __forceinline__ void ldm_x4(uint32_t* r, uint32_t addr) {
    asm volatile("ldmatrix.sync.aligned.m8n8.x4.shared.b16 {%0,%1,%2,%3}, [%4];"
                 : "=r"(r[0]), "=r"(r[1]), "=r"(r[2]), "=r"(r[3]) : "r"(addr));
}

__device__ __forceinline__ void cpa16(uint32_t d, const void* s) {
    asm volatile("cp.async.cg.shared.global [%0], [%1], 16;" :: "r"(d), "l"(s));
}

// ---- packed f32x2 helpers (sm_100+; exact fp32, double-rate) ----
__device__ __forceinline__ unsigned long long pk2(float lo, float hi) {
    unsigned long long r;
    asm("mov.b64 %0, {%1, %2};" : "=l"(r) : "f"(lo), "f"(hi));
    return r;
}
__device__ __forceinline__ void upk2(float& lo, float& hi, unsigned long long v) {
    asm("mov.b64 {%0, %1}, %2;" : "=f"(lo), "=f"(hi) : "l"(v));
}
__device__ __forceinline__ unsigned long long add2(unsigned long long a, unsigned long long b) {
    unsigned long long r;
    asm("add.rn.f32x2 %0, %1, %2;" : "=l"(r) : "l"(a), "l"(b));
    return r;
}
__device__ __forceinline__ unsigned long long mul2(unsigned long long a, unsigned long long b) {
    unsigned long long r;
    asm("mul.rn.f32x2 %0, %1, %2;" : "=l"(r) : "l"(a), "l"(b));
    return r;
}
__device__ __forceinline__ unsigned long long fma2(unsigned long long a, unsigned long long b,
                                                   unsigned long long c) {
    unsigned long long r;
    asm("fma.rn.f32x2 %0, %1, %2, %3;" : "=l"(r) : "l"(a), "l"(b), "l"(c));
    return r;
}
__device__ __forceinline__ float ex2f(float p) {
    float e;
    asm("ex2.approx.f32 %0, %1;" : "=f"(e) : "f"(p));
    return e;
}

// kern pair: two entries {g0,g1} with squared-norm sums {sq0,sq1}
__device__ __forceinline__ unsigned long long kern_pair(unsigned long long sq2,
                                                        unsigned long long g,
                                                        unsigned long long n2,
                                                        unsigned long long c1v) {
    unsigned long long d = fma2(g, n2, sq2);     // sq - 2g
    unsigned long long p = mul2(d, c1v);
    float p0, p1;
    upk2(p0, p1, p);
    unsigned long long e = pk2(ex2f(p0), ex2f(p1));
    unsigned long long e2 = mul2(e, e);
    unsigned long long e4 = mul2(e2, e2);
    unsigned long long e8 = mul2(e4, e4);
    unsigned long long e16 = mul2(e8, e8);
    return add2(add2(add2(e, e2), add2(e4, e8)), e16);
}

// ---------------- main: 3-stage GEMM + packed RBF epilogue + last-CTA reduce ----------
// 256 threads = 8 warps (4x2), warp tile 32x64, CTA tile 128x128, K-chunk 64, 3 stages.
__global__ __launch_bounds__(256, 2) void mmd_main(float* __restrict__ out) {
    extern __shared__ __half dsm[];
    __shared__ float sSqA[128], sSqB[128];
    __shared__ int s_last;
    // post-GEMM overlays into dynamic smem (stage data dead by then)
    double* swr = (double*)dsm;            // 8 doubles
    double* shv = (double*)dsm + 8;        // 256 doubles

    // triangular tile decode: bm <= bn
    int rem = blockIdx.x, bm = 0;
    while (rem >= NTILE - bm) { rem -= NTILE - bm; bm++; }
    int bn = bm + rem;

    int tid = threadIdx.x;
    int warp = tid >> 5, lane = tid & 31;
    int wm = warp >> 1, wn = warp & 1;        // 4x2 warp grid, warp tile 32x64
    int lane4 = lane >> 2;                    // 0..7
    int q2 = (lane & 3) * 2;                  // 0,2,4,6
    int l8 = lane & 7;

    if (tid < 128) sSqA[tid] = g_sq[bm * 128 + tid];
    else           sSqB[tid - 128] = g_sq[bn * 128 + (tid - 128)];

    uint32_t u0 = (uint32_t)__cvta_generic_to_shared(dsm);

    int aoff = (wm * 32 + ((lane >> 3) & 1) * 8 + l8) * SS + (lane >> 4) * 8;
    int boff = (wn * 64 + ((lane >> 4) & 1) * 8 + l8) * SS + ((lane >> 3) & 1) * 8;

    float acc[2][8][4];
#pragma unroll
    for (int mf = 0; mf < 2; mf++)
#pragma unroll
        for (int nf = 0; nf < 8; nf++)
#pragma unroll
            for (int k = 0; k < 4; k++) acc[mf][nf][k] = 0.f;

    const size_t gAbase = (size_t)bm * 128 * DIM;
    const size_t gBbase = (size_t)bn * 128 * DIM;

    // stage st: A tile at u0 + st*STGB, B tile at +2*STAGE bytes
#define LOAD_CHUNK(kc, st)                                                     \
    {                                                                          \
        _Pragma("unroll")                                                      \
        for (int it = 0; it < 4; it++) {                                       \
            int idx = tid + it * 256;          /* 0..1023 */                   \
            int row = idx >> 3, seg = idx & 7;                                 \
            size_t go = (size_t)row * DIM + (kc) * 64 + seg * 8;               \
            uint32_t so = (uint32_t)((st) * STGB + (row * SS + seg * 8) * 2);  \
            cpa16(u0 + so, g_Xh + gAbase + go);                                \
            cpa16(u0 + so + 2 * STAGE, g_Xh + gBbase + go);                    \
        }                                                                      \
        asm volatile("cp.async.commit_group;" ::: "memory");                   \
    }

    LOAD_CHUNK(0, 0);
    LOAD_CHUNK(1, 1);

#pragma unroll
    for (int kc = 0; kc < 4; kc++) {   // K = 256 in chunks of 64, 3-stage ring
        int st = kc % 3;
        if (kc < 3) asm volatile("cp.async.wait_group 1;" ::: "memory");
        else        asm volatile("cp.async.wait_group 0;" ::: "memory");
        __syncthreads();               // single barrier per chunk

        // prefetch chunk kc+2 into stage (kc+2)%3 (consumed at iter kc-1: safe)
        if (kc + 2 < 4) LOAD_CHUNK(kc + 2, (kc + 2) % 3);

        uint32_t base = u0 + (uint32_t)(st * STGB);
#pragma unroll
        for (int ks = 0; ks < 4; ks++) {       // four k16 steps per chunk
            uint32_t kofs = base + (uint32_t)(ks * 32);
            uint32_t ah[2][4], bh[4][4];
#pragma unroll
            for (int mf = 0; mf < 2; mf++)
                ldm_x4(ah[mf], kofs + (uint32_t)((aoff + mf * 16 * SS) * 2));
#pragma unroll
            for (int p = 0; p < 4; p++)
                ldm_x4(bh[p], kofs + (uint32_t)(2 * STAGE) + (uint32_t)((boff + p * 16 * SS) * 2));
#pragma unroll
            for (int p = 0; p < 4; p++) {
#pragma unroll
                for (int mf = 0; mf < 2; mf++) mma16816(acc[mf][2 * p],     ah[mf], bh[p]);
#pragma unroll
                for (int mf = 0; mf < 2; mf++) mma16816(acc[mf][2 * p + 1], ah[mf], bh[p] + 2);
            }
        }
    }

    // ------- fused packed-f32x2 epilogue: distances -> 5-kernel RBF sum -------
    float c1 = g_c1;
    unsigned long long c1v = pk2(c1, c1);
    unsigned long long n2  = pk2(-2.f, -2.f);
    unsigned long long wacc = pk2(0.f, 0.f);
    int r0 = wm * 32 + lane4;
#pragma unroll
    for (int mf = 0; mf < 2; mf++)
#pragma unroll
        for (int nf = 0; nf < 8; nf++) {
            int rA = r0 + mf * 16;
            int c0 = wn * 64 + nf * 8 + q2;
            float s0 = sSqA[rA], s1 = sSqA[rA + 8];
            float t0 = sSqB[c0], t1 = sSqB[c0 + 1];
            unsigned long long t01 = pk2(t0, t1);
            unsigned long long sq01 = add2(pk2(s0, s0), t01);
            unsigned long long sq23 = add2(pk2(s1, s1), t01);
            unsigned long long g01 = pk2(acc[mf][nf][0], acc[mf][nf][1]);
            unsigned long long g23 = pk2(acc[mf][nf][2], acc[mf][nf][3]);
            wacc = add2(wacc, kern_pair(sq01, g01, n2, c1v));
            wacc = add2(wacc, kern_pair(sq23, g23, n2, c1v));
        }
    float wlo, whi;
    upk2(wlo, whi, wacc);
    float wsum = wlo + whi;

    // quadrant sign (+ for s2s/t2t, - for cross) and x2 for off-diagonal tiles
    double w = (double)wsum;
    if ((bm < 32) != (bn < 32)) w = -w;
    if (bm != bn) w *= 2.0;
#pragma unroll
    for (int o = 16; o; o >>= 1) w += __shfl_down_sync(0xffffffffu, w, o);

    __syncthreads();                 // all GEMM smem reads done: overlay swr/shv safe
    if (lane == 0) swr[warp] = w;
    __syncthreads();
    if (tid == 0) {
        double tot = 0.0;
#pragma unroll
        for (int i = 0; i < 8; i++) tot += swr[i];
        g_Wpart[blockIdx.x] = tot;
        __threadfence();                       // release (writer thread only)
        unsigned old = atomicAdd(&g_ctrM, 1u);
        s_last = (old == NBLK - 1) ? 1 : 0;
    }
    __syncthreads();

    if (s_last) {
        __threadfence();                       // acquire (one CTA only)
        double a0 = 0.0, a1 = 0.0;
        for (int i = tid; i < NBLK; i += 512) {          // fixed order, 2 chains
            a0 += g_Wpart[i];
            if (i + 256 < NBLK) a1 += g_Wpart[i + 256];
        }
        shv[tid] = a0 + a1;
        __syncthreads();
        for (int o = 128; o; o >>= 1) {
            if (tid < o) shv[tid] += shv[tid + o];
            __syncthreads();
        }
        if (tid == 0) {
            out[0] = (float)(shv[0] / (5.0 * (double)BHALF * (double)BHALF));
            g_ctrM = 0;   // reset for next graph replay
        }
    }
}

// ---------------- launch ----------------
extern "C" void kernel_launch(void* const* d_in, const int* in_sizes, int n_in,
                              void* d_out, int out_size) {
    const float* s = (const float*)d_in[0];
    const float* t = (const float*)d_in[1];
    float* out = (float*)d_out;

    cudaFuncSetAttribute(mmd_main, cudaFuncAttributeMaxDynamicSharedMemorySize, SMEM_BYTES);

    prep_rows<<<NROWS / 8, 256>>>(s, t);
    prep_cols<<<CB, 256>>>(s, t);
    prep_scalar<<<1, 256>>>();
    mmd_main<<<NBLK, 256, SMEM_BYTES>>>(out);
}

// round 16
// speedup vs baseline: 1.0031x; 1.0031x over previous
#include <cuda_runtime.h>
#include <cuda_fp16.h>
#include <cstdint>

#define NROWS 8192
#define BHALF 4096
#define DIM   256
#define SS    72            // smem row stride (fp16): 64 data + 8 pad, conflict-free
#define STAGE (128 * SS)    // elems per array per pipeline stage (K=64 chunk)
#define NTILE 64
#define NBLK  2080          // upper-triangular 64x64 tile count
#define SMEM_BYTES (2 * 2 * STAGE * 2)   // 2 arrays x 2 stages x fp16 = 73728 B
#define PB 256              // prep blocks (blocks 0..255 do the prep slice)

// ---------------- scratch (device globals; no allocation) ----------------
__device__ __half g_Xh[NROWS * DIM];
__device__ float  g_sq[NROWS];
__device__ float  g_colpart[PB * DIM];
__device__ float  g_c1;            // -g0 * log2(e)
__device__ double g_Wpart[NBLK];
__device__ unsigned g_ctrP;        // prep completion ticket
__device__ unsigned g_flag;        // prep+scalar ready
__device__ unsigned g_ctrM;        // main completion ticket

// ---------------- asm helpers ----------------
__device__ __forceinline__ void mma16816(float* c, const uint32_t* a, const uint32_t* b) {
    asm volatile(
        "mma.sync.aligned.m16n8k16.row.col.f32.f16.f16.f32 "
        "{%0,%1,%2,%3},{%4,%5,%6,%7},{%8,%9},{%0,%1,%2,%3};"
        : "+f"(c[0]), "+f"(c[1]), "+f"(c[2]), "+f"(c[3])
        : "r"(a[0]), "r"(a[1]), "r"(a[2]), "r"(a[3]), "r"(b[0]), "r"(b[1]));
}

__device__ __forceinline__ void ldm_x4(uint32_t* r, uint32_t addr) {
    asm volatile("ldmatrix.sync.aligned.m8n8.x4.shared.b16 {%0,%1,%2,%3}, [%4];"
                 : "=r"(r[0]), "=r"(r[1]), "=r"(r[2]), "=r"(r[3]) : "r"(addr));
}

__device__ __forceinline__ void cpa16(uint32_t d, const void* s) {
    asm volatile("cp.async.cg.shared.global [%0], [%1], 16;" :: "r"(d), "l"(s));
}

// ---- packed f32x2 helpers (sm_100+; exact fp32, double-rate) ----
__device__ __forceinline__ unsigned long long pk2(float lo, float hi) {
    unsigned long long r;
    asm("mov.b64 %0, {%1, %2};" : "=l"(r) : "f"(lo), "f"(hi));
    return r;
}
__device__ __forceinline__ void upk2(float& lo, float& hi, unsigned long long v) {
    asm("mov.b64 {%0, %1}, %2;" : "=f"(lo), "=f"(hi) : "l"(v));
}
__device__ __forceinline__ unsigned long long add2(unsigned long long a, unsigned long long b) {
    unsigned long long r;
    asm("add.rn.f32x2 %0, %1, %2;" : "=l"(r) : "l"(a), "l"(b));
    return r;
}
__device__ __forceinline__ unsigned long long mul2(unsigned long long a, unsigned long long b) {
    unsigned long long r;
    asm("mul.rn.f32x2 %0, %1, %2;" : "=l"(r) : "l"(a), "l"(b));
    return r;
}
__device__ __forceinline__ unsigned long long fma2(unsigned long long a, unsigned long long b,
                                                   unsigned long long c) {
    unsigned long long r;
    asm("fma.rn.f32x2 %0, %1, %2, %3;" : "=l"(r) : "l"(a), "l"(b), "l"(c));
    return r;
}
__device__ __forceinline__ float ex2f(float p) {
    float e;
    asm("ex2.approx.f32 %0, %1;" : "=f"(e) : "f"(p));
    return e;
}

// kern pair: two entries {g0,g1} with squared-norm sums {sq0,sq1}
__device__ __forceinline__ unsigned long long kern_pair(unsigned long long sq2,
                                                        unsigned long long g,
                                                        unsigned long long n2,
                                                        unsigned long long c1v) {
    unsigned long long d = fma2(g, n2, sq2);     // sq - 2g
    unsigned long long p = mul2(d, c1v);
    float p0, p1;
    upk2(p0, p1, p);
    unsigned long long e = pk2(ex2f(p0), ex2f(p1));
    unsigned long long e2 = mul2(e, e);
    unsigned long long e4 = mul2(e2, e2);
    unsigned long long e8 = mul2(e4, e4);
    unsigned long long e16 = mul2(e8, e8);
    return add2(add2(add2(e, e2), add2(e4, e8)), e16);
}

// ---------------- single-launch fused kernel: prep (blocks<PB) + flag + GEMM tile ----
// 256 threads = 8 warps (4x2), warp tile 32x64, CTA tile 128x128, K-chunk 64, 2 stages.
__global__ __launch_bounds__(256, 2) void mmd_all(const float* __restrict__ s,
                                                  const float* __restrict__ t,
                                                  float* __restrict__ out) {
    extern __shared__ __half dsm[];
    __half* sA = dsm;                  // A fp16 (2 stages)
    __half* sB = dsm + 2 * STAGE;      // B fp16 (2 stages)
    __shared__ float sSqA[128], sSqB[128];
    __shared__ double swr[8];
    __shared__ double sh[256];
    __shared__ int s_last;

    int tid = threadIdx.x, warp = tid >> 5, lane = tid & 31;
    int bx = blockIdx.x;

    // ---------- Phase A: prep slice (first PB blocks; first-wave resident) ----------
    if (bx < PB) {
        float colsum[8] = {0.f, 0.f, 0.f, 0.f, 0.f, 0.f, 0.f, 0.f};
#pragma unroll
        for (int i = 0; i < 4; i++) {
            int row = bx * 32 + warp * 4 + i;
            const float* src = (row < BHALF) ? (s + (size_t)row * DIM)
                                             : (t + (size_t)(row - BHALF) * DIM);
            float4 v0 = *(const float4*)(src + lane * 8);
            float4 v1 = *(const float4*)(src + lane * 8 + 4);
            float v[8] = {v0.x, v0.y, v0.z, v0.w, v1.x, v1.y, v1.z, v1.w};
            float sq = 0.f;
            unsigned hu[4];
#pragma unroll
            for (int j = 0; j < 4; j++) {
                float a = v[2 * j], b = v[2 * j + 1];
                sq = fmaf(a, a, sq);
                sq = fmaf(b, b, sq);
                colsum[2 * j]     += a;
                colsum[2 * j + 1] += b;
                hu[j] = (unsigned)__half_as_ushort(__float2half_rn(a)) |
                        ((unsigned)__half_as_ushort(__float2half_rn(b)) << 16);
            }
            *(uint4*)(g_Xh + (size_t)row * DIM + lane * 8) =
                make_uint4(hu[0], hu[1], hu[2], hu[3]);
#pragma unroll
            for (int o = 16; o; o >>= 1) sq += __shfl_xor_sync(0xffffffffu, sq, o);
            if (lane == 0) g_sq[row] = sq;
        }
        float* scol = (float*)dsm;     // overlay GEMM smem as [8][256] scratch
#pragma unroll
        for (int j = 0; j < 8; j++) scol[warp * 256 + lane * 8 + j] = colsum[j];
        __syncthreads();
        float a = 0.f;
#pragma unroll
        for (int w8 = 0; w8 < 8; w8++) a += scol[w8 * 256 + tid];
        g_colpart[bx * DIM + tid] = a;

        __threadfence();
        __syncthreads();
        if (tid == 0) {
            unsigned old = atomicAdd(&g_ctrP, 1u);
            s_last = (old == PB - 1) ? 1 : 0;
        }
        __syncthreads();

        if (s_last) {   // 256th finisher: bandwidth scalar (MLP-8 chains), then release
            __threadfence();
            double S0 = 0, S1 = 0, S2 = 0, S3 = 0, S4 = 0, S5 = 0, S6 = 0, S7 = 0;
#pragma unroll
            for (int i = 0; i < 32; i += 8) {
                S0 += (double)g_sq[tid + (i + 0) * 256];
                S1 += (double)g_sq[tid + (i + 1) * 256];
                S2 += (double)g_sq[tid + (i + 2) * 256];
                S3 += (double)g_sq[tid + (i + 3) * 256];
                S4 += (double)g_sq[tid + (i + 4) * 256];
                S5 += (double)g_sq[tid + (i + 5) * 256];
                S6 += (double)g_sq[tid + (i + 6) * 256];
                S7 += (double)g_sq[tid + (i + 7) * 256];
            }
            double S = ((S0 + S1) + (S2 + S3)) + ((S4 + S5) + (S6 + S7));

            double c0 = 0, c1_ = 0, c2 = 0, c3 = 0, c4 = 0, c5 = 0, c6 = 0, c7 = 0;
#pragma unroll 4
            for (int b = 0; b < PB; b += 8) {
                c0 += (double)g_colpart[(b + 0) * DIM + tid];
                c1_ += (double)g_colpart[(b + 1) * DIM + tid];
                c2 += (double)g_colpart[(b + 2) * DIM + tid];
                c3 += (double)g_colpart[(b + 3) * DIM + tid];
                c4 += (double)g_colpart[(b + 4) * DIM + tid];
                c5 += (double)g_colpart[(b + 5) * DIM + tid];
                c6 += (double)g_colpart[(b + 6) * DIM + tid];
                c7 += (double)g_colpart[(b + 7) * DIM + tid];
            }
            double c = ((c0 + c1_) + (c2 + c3)) + ((c4 + c5) + (c6 + c7));

            sh[tid] = 2.0 * (double)NROWS * S - 2.0 * c * c;
            __syncthreads();
            for (int o = 128; o; o >>= 1) {
                if (tid < o) sh[tid] += sh[tid + o];
                __syncthreads();
            }
            if (tid == 0) {
                double bw = ((double)NROWS * (double)NROWS - (double)NROWS) / sh[0];
                bw *= 0.25;  // / 2^(NUM_KERNELS//2)
                g_c1 = (float)(-bw * 1.4426950408889634);
                __threadfence();
                atomicExch(&g_flag, 1u);       // release
            }
        }
        __syncthreads();   // prep smem overlay dead before GEMM reuses it
    }

    // ---------- gate: wait for prep+scalar (later waves find flag set) ----------
    if (tid == 0) {
        while (atomicAdd(&g_flag, 0u) == 0u) { __nanosleep(64); }
    }
    __syncthreads();
    __threadfence();                           // acquire for g_Xh / g_sq / g_c1

    // ---------- Phase B: one 128x128 triangular tile (R14 GEMM, unchanged) ----------
    int rem = bx, bm = 0;
    while (rem >= NTILE - bm) { rem -= NTILE - bm; bm++; }
    int bn = bm + rem;

    int wm = warp >> 1, wn = warp & 1;        // 4x2 warp grid, warp tile 32x64
    int lane4 = lane >> 2;
    int q2 = (lane & 3) * 2;
    int l8 = lane & 7;

    if (tid < 128) sSqA[tid] = g_sq[bm * 128 + tid];
    else           sSqB[tid - 128] = g_sq[bn * 128 + (tid - 128)];

    uint32_t uA = (uint32_t)__cvta_generic_to_shared(sA);
    uint32_t uB = (uint32_t)__cvta_generic_to_shared(sB);

    int aoff = (wm * 32 + ((lane >> 3) & 1) * 8 + l8) * SS + (lane >> 4) * 8;
    int boff = (wn * 64 + ((lane >> 4) & 1) * 8 + l8) * SS + ((lane >> 3) & 1) * 8;

    float acc[2][8][4];
#pragma unroll
    for (int mf = 0; mf < 2; mf++)
#pragma unroll
        for (int nf = 0; nf < 8; nf++)
#pragma unroll
            for (int k = 0; k < 4; k++) acc[mf][nf][k] = 0.f;

    const size_t gAbase = (size_t)bm * 128 * DIM;
    const size_t gBbase = (size_t)bn * 128 * DIM;

#define LOAD_CHUNK(kc, st)                                                     \
    {                                                                          \
        _Pragma("unroll")                                                      \
        for (int it = 0; it < 4; it++) {                                       \
            int idx = tid + it * 256;          /* 0..1023 */                   \
            int row = idx >> 3, seg = idx & 7;                                 \
            size_t go = (size_t)row * DIM + (kc) * 64 + seg * 8;               \
            uint32_t so = (uint32_t)((st) * STAGE + row * SS + seg * 8) * 2;   \
            cpa16(uA + so, g_Xh + gAbase + go);                                \
            cpa16(uB + so, g_Xh + gBbase + go);                                \
        }                                                                      \
        asm volatile("cp.async.commit_group;" ::: "memory");                   \
    }

    LOAD_CHUNK(0, 0);
    LOAD_CHUNK(1, 1);

    for (int kc = 0; kc < 4; kc++) {   // K = 256 in chunks of 64
        int st = kc & 1;
        if (kc < 3) asm volatile("cp.async.wait_group 1;" ::: "memory");
        else        asm volatile("cp.async.wait_group 0;" ::: "memory");
        __syncthreads();

        uint32_t stB = (uint32_t)(st * STAGE) * 2;
#pragma unroll
        for (int ks = 0; ks < 4; ks++) {       // four k16 steps per chunk
            uint32_t kofs = stB + (uint32_t)(ks * 16) * 2;
            uint32_t ah[2][4], bh[4][4];
#pragma unroll
            for (int mf = 0; mf < 2; mf++)
                ldm_x4(ah[mf], uA + kofs + (uint32_t)((aoff + mf * 16 * SS) * 2));
#pragma unroll
            for (int p = 0; p < 4; p++)
                ldm_x4(bh[p], uB + kofs + (uint32_t)((boff + p * 16 * SS) * 2));
#pragma unroll
            for (int p = 0; p < 4; p++) {
#pragma unroll
                for (int mf = 0; mf < 2; mf++) mma16816(acc[mf][2 * p],     ah[mf], bh[p]);
#pragma unroll
                for (int mf = 0; mf < 2; mf++) mma16816(acc[mf][2 * p + 1], ah[mf], bh[p] + 2);
            }
        }
        __syncthreads();

        if (kc + 2 < 4) LOAD_CHUNK(kc + 2, st);
    }

    // ------- fused packed-f32x2 epilogue: distances -> 5-kernel RBF sum -------
    float c1 = g_c1;
    unsigned long long c1v = pk2(c1, c1);
    unsigned long long n2  = pk2(-2.f, -2.f);
    unsigned long long wacc = pk2(0.f, 0.f);
    int r0 = wm * 32 + lane4;
#pragma unroll
    for (int mf = 0; mf < 2; mf++)
#pragma unroll
        for (int nf = 0; nf < 8; nf++) {
            int rA = r0 + mf * 16;
            int c0 = wn * 64 + nf * 8 + q2;
            float s0 = sSqA[rA], s1 = sSqA[rA + 8];
            float t0 = sSqB[c0], t1 = sSqB[c0 + 1];
            unsigned long long t01 = pk2(t0, t1);
            unsigned long long sq01 = add2(pk2(s0, s0), t01);
            unsigned long long sq23 = add2(pk2(s1, s1), t01);
            unsigned long long g01 = pk2(acc[mf][nf][0], acc[mf][nf][1]);
            unsigned long long g23 = pk2(acc[mf][nf][2], acc[mf][nf][3]);
            wacc = add2(wacc, kern_pair(sq01, g01, n2, c1v));
            wacc = add2(wacc, kern_pair(sq23, g23, n2, c1v));
        }
    float wlo, whi;
    upk2(wlo, whi, wacc);
    float wsum = wlo + whi;

    // quadrant sign (+ for s2s/t2t, - for cross) and x2 for off-diagonal tiles
    double w = (double)wsum;
    if ((bm < 32) != (bn < 32)) w = -w;
    if (bm != bn) w *= 2.0;
#pragma unroll
    for (int o = 16; o; o >>= 1) w += __shfl_down_sync(0xffffffffu, w, o);
    if (lane == 0) swr[warp] = w;
    __syncthreads();
    if (tid == 0) {
        double tot = 0.0;
#pragma unroll
        for (int i = 0; i < 8; i++) tot += swr[i];
        g_Wpart[bx] = tot;
        __threadfence();                       // release (writer thread only)
        unsigned old = atomicAdd(&g_ctrM, 1u);
        s_last = (old == NBLK - 1) ? 1 : 0;
    }
    __syncthreads();

    if (s_last) {
        __threadfence();                       // acquire (one CTA only)
        double a0 = 0.0, a1 = 0.0;
        for (int i = tid; i < NBLK; i += 512) {          // fixed order, 2 chains
            a0 += g_Wpart[i];
            if (i + 256 < NBLK) a1 += g_Wpart[i + 256];
        }
        sh[tid] = a0 + a1;
        __syncthreads();
        for (int o = 128; o; o >>= 1) {
            if (tid < o) sh[tid] += sh[tid + o];
            __syncthreads();
        }
        if (tid == 0) {
            out[0] = (float)(sh[0] / (5.0 * (double)BHALF * (double)BHALF));
            g_ctrM = 0;        // reset for next graph replay (deterministic)
            g_ctrP = 0;
            g_flag = 0;
        }
    }
}

// ---------------- launch ----------------
extern "C" void kernel_launch(void* const* d_in, const int* in_sizes, int n_in,
                              void* d_out, int out_size) {
    const float* s = (const float*)d_in[0];
    const float* t = (const float*)d_in[1];
    float* out = (float*)d_out;

    cudaFuncSetAttribute(mmd_all, cudaFuncAttributeMaxDynamicSharedMemorySize, SMEM_BYTES);
    mmd_all<<<NBLK, 256, SMEM_BYTES>>>(s, t, out);
}

// round 17
// speedup vs baseline: 1.0395x; 1.0363x over previous
#include <cuda_runtime.h>
#include <cuda_fp16.h>
#include <cstdint>

#define NROWS 8192
#define BHALF 4096
#define DIM   256
#define SS    72            // smem row stride (fp16): 64 data + 8 pad, conflict-free
#define STAGE (128 * SS)    // elems per array per pipeline stage (K=64 chunk)
#define NTILE 64
#define NBLK  2080          // upper-triangular 64x64 tile count
#define SMEM_BYTES (2 * 2 * STAGE * 2)   // 2 arrays x 2 stages x fp16 = 73728 B
#define PB 256              // prep blocks

// ---------------- scratch (device globals; no allocation) ----------------
__device__ __half g_Xh[NROWS * DIM];
__device__ float  g_sq[NROWS];
__device__ float  g_colpart[PB * DIM];
__device__ float  g_c1;            // -g0 * log2(e)
__device__ double g_Wpart[NBLK];
__device__ unsigned g_flag;        // scalar ready
__device__ unsigned g_ctrM;        // main completion ticket

// ---------------- launch 1: prep (fp16 image + row norms + column partials) --------
// 256 blocks x 256 threads; block handles 32 rows (4 per warp). No scalar tail.
__global__ __launch_bounds__(256) void prep_fused(const float* __restrict__ s,
                                                  const float* __restrict__ t) {
    __shared__ float scol[8][256];
    int warp = threadIdx.x >> 5, lane = threadIdx.x & 31;
    int tid = threadIdx.x;

    float colsum[8] = {0.f, 0.f, 0.f, 0.f, 0.f, 0.f, 0.f, 0.f};
#pragma unroll
    for (int i = 0; i < 4; i++) {
        int row = blockIdx.x * 32 + warp * 4 + i;
        const float* src = (row < BHALF) ? (s + (size_t)row * DIM)
                                         : (t + (size_t)(row - BHALF) * DIM);
        float4 v0 = *(const float4*)(src + lane * 8);
        float4 v1 = *(const float4*)(src + lane * 8 + 4);
        float v[8] = {v0.x, v0.y, v0.z, v0.w, v1.x, v1.y, v1.z, v1.w};

        float sq = 0.f;
        unsigned hu[4];
#pragma unroll
        for (int j = 0; j < 4; j++) {
            float a = v[2 * j], b = v[2 * j + 1];
            sq = fmaf(a, a, sq);
            sq = fmaf(b, b, sq);
            colsum[2 * j]     += a;
            colsum[2 * j + 1] += b;
            hu[j] = (unsigned)__half_as_ushort(__float2half_rn(a)) |
                    ((unsigned)__half_as_ushort(__float2half_rn(b)) << 16);
        }
        *(uint4*)(g_Xh + (size_t)row * DIM + lane * 8) = make_uint4(hu[0], hu[1], hu[2], hu[3]);
#pragma unroll
        for (int o = 16; o; o >>= 1) sq += __shfl_xor_sync(0xffffffffu, sq, o);
        if (lane == 0) g_sq[row] = sq;
    }
#pragma unroll
    for (int j = 0; j < 8; j++) scol[warp][lane * 8 + j] = colsum[j];
    __syncthreads();
    float a = 0.f;
#pragma unroll
    for (int w = 0; w < 8; w++) a += scol[w][tid];
    g_colpart[blockIdx.x * DIM + tid] = a;
}

// ---------------- asm helpers ----------------
__device__ __forceinline__ void mma16816(float* c, const uint32_t* a, const uint32_t* b) {
    asm volatile(
        "mma.sync.aligned.m16n8k16.row.col.f32.f16.f16.f32 "
        "{%0,%1,%2,%3},{%4,%5,%6,%7},{%8,%9},{%0,%1,%2,%3};"
        : "+f"(c[0]), "+f"(c[1]), "+f"(c[2]), "+f"(c[3])
        : "r"(a[0]), "r"(a[1]), "r"(a[2]), "r"(a[3]), "r"(b[0]), "r"(b[1]));
}

__device__ __forceinline__ void ldm_x4(uint32_t* r, uint32_t addr) {
    asm volatile("ldmatrix.sync.aligned.m8n8.x4.shared.b16 {%0,%1,%2,%3}, [%4];"
                 : "=r"(r[0]), "=r"(r[1]), "=r"(r[2]), "=r"(r[3]) : "r"(addr));
}

__device__ __forceinline__ void cpa16(uint32_t d, const void* s) {
    asm volatile("cp.async.cg.shared.global [%0], [%1], 16;" :: "r"(d), "l"(s));
}

// ---- packed f32x2 helpers (sm_100+; exact fp32, double-rate) ----
__device__ __forceinline__ unsigned long long pk2(float lo, float hi) {
    unsigned long long r;
    asm("mov.b64 %0, {%1, %2};" : "=l"(r) : "f"(lo), "f"(hi));
    return r;
}
__device__ __forceinline__ void upk2(float& lo, float& hi, unsigned long long v) {
    asm("mov.b64 {%0, %1}, %2;" : "=f"(lo), "=f"(hi) : "l"(v));
}
__device__ __forceinline__ unsigned long long add2(unsigned long long a, unsigned long long b) {
    unsigned long long r;
    asm("add.rn.f32x2 %0, %1, %2;" : "=l"(r) : "l"(a), "l"(b));
    return r;
}
__device__ __forceinline__ unsigned long long mul2(unsigned long long a, unsigned long long b) {
    unsigned long long r;
    asm("mul.rn.f32x2 %0, %1, %2;" : "=l"(r) : "l"(a), "l"(b));
    return r;
}
__device__ __forceinline__ unsigned long long fma2(unsigned long long a, unsigned long long b,
                                                   unsigned long long c) {
    unsigned long long r;
    asm("fma.rn.f32x2 %0, %1, %2, %3;" : "=l"(r) : "l"(a), "l"(b), "l"(c));
    return r;
}
__device__ __forceinline__ float ex2f(float p) {
    float e;
    asm("ex2.approx.f32 %0, %1;" : "=f"(e) : "f"(p));
    return e;
}

// kern pair: two entries {g0,g1} with squared-norm sums {sq0,sq1}
__device__ __forceinline__ unsigned long long kern_pair(unsigned long long sq2,
                                                        unsigned long long g,
                                                        unsigned long long n2,
                                                        unsigned long long c1v) {
    unsigned long long d = fma2(g, n2, sq2);     // sq - 2g
    unsigned long long p = mul2(d, c1v);
    float p0, p1;
    upk2(p0, p1, p);
    unsigned long long e = pk2(ex2f(p0), ex2f(p1));
    unsigned long long e2 = mul2(e, e);
    unsigned long long e4 = mul2(e2, e2);
    unsigned long long e8 = mul2(e4, e4);
    unsigned long long e16 = mul2(e8, e8);
    return add2(add2(add2(e, e2), add2(e4, e8)), e16);
}

// ---------------- launch 2: GEMM + hidden scalar + packed epilogue + reduce --------
// 256 threads = 8 warps (4x2), warp tile 32x64, CTA tile 128x128, K-chunk 64.
__global__ __launch_bounds__(256, 2) void mmd_main(float* __restrict__ out) {
    extern __shared__ __half dsm[];
    __half* sA = dsm;                  // A fp16 (2 stages)
    __half* sB = dsm + 2 * STAGE;      // B fp16 (2 stages)
    __shared__ float sSqA[128], sSqB[128];
    __shared__ double swr[8];
    __shared__ double sh[256];
    __shared__ float s_c1;
    __shared__ int s_last;

    int tid = threadIdx.x;
    int warp = tid >> 5, lane = tid & 31;
    int bx = blockIdx.x;

    // ----- block 0: bandwidth scalar FIRST (overlaps other CTAs' first tiles) -----
    if (bx == 0) {
        double S0 = 0, S1 = 0, S2 = 0, S3 = 0, S4 = 0, S5 = 0, S6 = 0, S7 = 0;
#pragma unroll
        for (int i = 0; i < 32; i += 8) {
            S0 += (double)g_sq[tid + (i + 0) * 256];
            S1 += (double)g_sq[tid + (i + 1) * 256];
            S2 += (double)g_sq[tid + (i + 2) * 256];
            S3 += (double)g_sq[tid + (i + 3) * 256];
            S4 += (double)g_sq[tid + (i + 4) * 256];
            S5 += (double)g_sq[tid + (i + 5) * 256];
            S6 += (double)g_sq[tid + (i + 6) * 256];
            S7 += (double)g_sq[tid + (i + 7) * 256];
        }
        double S = ((S0 + S1) + (S2 + S3)) + ((S4 + S5) + (S6 + S7));

        double c0 = 0, c1_ = 0, c2 = 0, c3 = 0, c4 = 0, c5 = 0, c6 = 0, c7 = 0;
#pragma unroll 4
        for (int b = 0; b < PB; b += 8) {
            c0 += (double)g_colpart[(b + 0) * DIM + tid];
            c1_ += (double)g_colpart[(b + 1) * DIM + tid];
            c2 += (double)g_colpart[(b + 2) * DIM + tid];
            c3 += (double)g_colpart[(b + 3) * DIM + tid];
            c4 += (double)g_colpart[(b + 4) * DIM + tid];
            c5 += (double)g_colpart[(b + 5) * DIM + tid];
            c6 += (double)g_colpart[(b + 6) * DIM + tid];
            c7 += (double)g_colpart[(b + 7) * DIM + tid];
        }
        double c = ((c0 + c1_) + (c2 + c3)) + ((c4 + c5) + (c6 + c7));

        sh[tid] = 2.0 * (double)NROWS * S - 2.0 * c * c;
        __syncthreads();
        for (int o = 128; o; o >>= 1) {
            if (tid < o) sh[tid] += sh[tid + o];
            __syncthreads();
        }
        if (tid == 0) {
            double bw = ((double)NROWS * (double)NROWS - (double)NROWS) / sh[0];
            bw *= 0.25;  // / 2^(NUM_KERNELS//2)
            g_c1 = (float)(-bw * 1.4426950408889634);
            __threadfence();
            atomicExch(&g_flag, 1u);   // release
        }
        __syncthreads();
    }

    // triangular tile decode: bm <= bn
    int rem = bx, bm = 0;
    while (rem >= NTILE - bm) { rem -= NTILE - bm; bm++; }
    int bn = bm + rem;

    int wm = warp >> 1, wn = warp & 1;        // 4x2 warp grid, warp tile 32x64
    int lane4 = lane >> 2;                    // 0..7
    int q2 = (lane & 3) * 2;                  // 0,2,4,6
    int l8 = lane & 7;

    if (tid < 128) sSqA[tid] = g_sq[bm * 128 + tid];
    else           sSqB[tid - 128] = g_sq[bn * 128 + (tid - 128)];

    uint32_t uA = (uint32_t)__cvta_generic_to_shared(sA);
    uint32_t uB = (uint32_t)__cvta_generic_to_shared(sB);

    int aoff = (wm * 32 + ((lane >> 3) & 1) * 8 + l8) * SS + (lane >> 4) * 8;
    int boff = (wn * 64 + ((lane >> 4) & 1) * 8 + l8) * SS + ((lane >> 3) & 1) * 8;

    float acc[2][8][4];
#pragma unroll
    for (int mf = 0; mf < 2; mf++)
#pragma unroll
        for (int nf = 0; nf < 8; nf++)
#pragma unroll
            for (int k = 0; k < 4; k++) acc[mf][nf][k] = 0.f;

    const size_t gAbase = (size_t)bm * 128 * DIM;
    const size_t gBbase = (size_t)bn * 128 * DIM;

#define LOAD_CHUNK(kc, st)                                                     \
    {                                                                          \
        _Pragma("unroll")                                                      \
        for (int it = 0; it < 4; it++) {                                       \
            int idx = tid + it * 256;          /* 0..1023 */                   \
            int row = idx >> 3, seg = idx & 7;                                 \
            size_t go = (size_t)row * DIM + (kc) * 64 + seg * 8;               \
            uint32_t so = (uint32_t)((st) * STAGE + row * SS + seg * 8) * 2;   \
            cpa16(uA + so, g_Xh + gAbase + go);                                \
            cpa16(uB + so, g_Xh + gBbase + go);                                \
        }                                                                      \
        asm volatile("cp.async.commit_group;" ::: "memory");                   \
    }

    LOAD_CHUNK(0, 0);
    LOAD_CHUNK(1, 1);

    for (int kc = 0; kc < 4; kc++) {   // K = 256 in chunks of 64
        int st = kc & 1;
        if (kc < 3) asm volatile("cp.async.wait_group 1;" ::: "memory");
        else        asm volatile("cp.async.wait_group 0;" ::: "memory");
        __syncthreads();

        uint32_t stB = (uint32_t)(st * STAGE) * 2;
#pragma unroll
        for (int ks = 0; ks < 4; ks++) {       // four k16 steps per chunk
            uint32_t kofs = stB + (uint32_t)(ks * 16) * 2;
            uint32_t ah[2][4], bh[4][4];
#pragma unroll
            for (int mf = 0; mf < 2; mf++)
                ldm_x4(ah[mf], uA + kofs + (uint32_t)((aoff + mf * 16 * SS) * 2));
#pragma unroll
            for (int p = 0; p < 4; p++)
                ldm_x4(bh[p], uB + kofs + (uint32_t)((boff + p * 16 * SS) * 2));
#pragma unroll
            for (int p = 0; p < 4; p++) {
#pragma unroll
                for (int mf = 0; mf < 2; mf++) mma16816(acc[mf][2 * p],     ah[mf], bh[p]);
#pragma unroll
                for (int mf = 0; mf < 2; mf++) mma16816(acc[mf][2 * p + 1], ah[mf], bh[p] + 2);
            }
        }
        __syncthreads();

        if (kc + 2 < 4) LOAD_CHUNK(kc + 2, st);
    }

    // ----- gate: scalar ready? (block 0 set it ~4us in; first tiles take longer) ----
    if (tid == 0) {
        while (atomicAdd(&g_flag, 0u) == 0u) { __nanosleep(32); }
        __threadfence();               // acquire
        s_c1 = g_c1;
    }
    __syncthreads();

    // ------- fused packed-f32x2 epilogue: distances -> 5-kernel RBF sum -------
    float c1 = s_c1;
    unsigned long long c1v = pk2(c1, c1);
    unsigned long long n2  = pk2(-2.f, -2.f);
    unsigned long long wacc = pk2(0.f, 0.f);
    int r0 = wm * 32 + lane4;
#pragma unroll
    for (int mf = 0; mf < 2; mf++)
#pragma unroll
        for (int nf = 0; nf < 8; nf++) {
            int rA = r0 + mf * 16;
            int c0 = wn * 64 + nf * 8 + q2;
            float s0 = sSqA[rA], s1 = sSqA[rA + 8];
            float t0 = sSqB[c0], t1 = sSqB[c0 + 1];
            unsigned long long t01 = pk2(t0, t1);
            unsigned long long sq01 = add2(pk2(s0, s0), t01);
            unsigned long long sq23 = add2(pk2(s1, s1), t01);
            unsigned long long g01 = pk2(acc[mf][nf][0], acc[mf][nf][1]);
            unsigned long long g23 = pk2(acc[mf][nf][2], acc[mf][nf][3]);
            wacc = add2(wacc, kern_pair(sq01, g01, n2, c1v));
            wacc = add2(wacc, kern_pair(sq23, g23, n2, c1v));
        }
    float wlo, whi;
    upk2(wlo, whi, wacc);
    float wsum = wlo + whi;

    // quadrant sign (+ for s2s/t2t, - for cross) and x2 for off-diagonal tiles
    double w = (double)wsum;
    if ((bm < 32) != (bn < 32)) w = -w;
    if (bm != bn) w *= 2.0;
#pragma unroll
    for (int o = 16; o; o >>= 1) w += __shfl_down_sync(0xffffffffu, w, o);
    if (lane == 0) swr[warp] = w;
    __syncthreads();
    if (tid == 0) {
        double tot = 0.0;
#pragma unroll
        for (int i = 0; i < 8; i++) tot += swr[i];
        g_Wpart[bx] = tot;
        __threadfence();                       // release (writer thread only)
        unsigned old = atomicAdd(&g_ctrM, 1u);
        s_last = (old == NBLK - 1) ? 1 : 0;
    }
    __syncthreads();

    if (s_last) {
        __threadfence();                       // acquire (one CTA only)
        double a0 = 0.0, a1 = 0.0;
        for (int i = tid; i < NBLK; i += 512) {          // fixed order, 2 chains
            a0 += g_Wpart[i];
            if (i + 256 < NBLK) a1 += g_Wpart[i + 256];
        }
        sh[tid] = a0 + a1;
        __syncthreads();
        for (int o = 128; o; o >>= 1) {
            if (tid < o) sh[tid] += sh[tid + o];
            __syncthreads();
        }
        if (tid == 0) {
            out[0] = (float)(sh[0] / (5.0 * (double)BHALF * (double)BHALF));
            g_ctrM = 0;        // reset for next graph replay (deterministic)
            g_flag = 0;
        }
    }
}

// ---------------- launch ----------------
extern "C" void kernel_launch(void* const* d_in, const int* in_sizes, int n_in,
                              void* d_out, int out_size) {
    const float* s = (const float*)d_in[0];
    const float* t = (const float*)d_in[1];
    float* out = (float*)d_out;

    cudaFuncSetAttribute(mmd_main, cudaFuncAttributeMaxDynamicSharedMemorySize, SMEM_BYTES);

    prep_fused<<<PB, 256>>>(s, t);
    mmd_main<<<NBLK, 256, SMEM_BYTES>>>(out);
}